// round 8
// baseline (speedup 1.0000x reference)
#include <cuda_runtime.h>

#define Bb 64
#define Tt 512
#define Ee 256
#define Uu 512
#define NG 2048   // 4*U
#define NBLK 128  // step-kernel grid: CTA owns 4 u-columns (all 4 gates)

// Scratch (device globals: allocation-free per harness rules)
__device__ float g_xp[(size_t)Tt * NG * Bb];          // [t][n][b], n = gate*U + u (256 MB)
__device__ __align__(16) unsigned long long g_hX[2][256 * Bb];  // h, k-pair transposed:
                                                      // [p][b] = (h[b][2p], h[b][2p+1])
__device__ float g_cX[Uu * Bb];                       // cell state, u-major (b contiguous)
__device__ __align__(16) unsigned long long g_wpack[NBLK * 4096]; // packed Wh (4 MB)

// ---------- packed f32x2 helpers (Blackwell FFMA2/FADD2) ----------
static __device__ __forceinline__ unsigned long long pack2(float a, float b) {
    unsigned long long r;
    unsigned ai = __float_as_uint(a), bi = __float_as_uint(b);
    asm("mov.b64 %0, {%1, %2};" : "=l"(r) : "r"(ai), "r"(bi));
    return r;
}
static __device__ __forceinline__ void unpack2(unsigned long long v, float& a, float& b) {
    unsigned ai, bi;
    asm("mov.b64 {%0, %1}, %2;" : "=r"(ai), "=r"(bi) : "l"(v));
    a = __uint_as_float(ai); b = __uint_as_float(bi);
}
static __device__ __forceinline__ unsigned long long ffma2(
    unsigned long long a, unsigned long long b, unsigned long long c) {
    unsigned long long d;
    asm("fma.rn.f32x2 %0, %1, %2, %3;" : "=l"(d) : "l"(a), "l"(b), "l"(c));
    return d;
}
static __device__ __forceinline__ unsigned long long add2(
    unsigned long long a, unsigned long long b) {
    unsigned long long d;
    asm("add.rn.f32x2 %0, %1, %2;" : "=l"(d) : "l"(a), "l"(b));
    return d;
}
static __device__ __forceinline__ float hadd2(unsigned long long v) {
    float a, b; unpack2(v, a, b); return a + b;
}

// =====================================================================================
// Kernel 1: x_proj (unchanged; proven). Output xp[t][n][b] (+bias), b contiguous.
// =====================================================================================
__global__ __launch_bounds__(256) void xproj_kernel(
    const float* __restrict__ inp,
    const float* __restrict__ W0, const float* __restrict__ W1,
    const float* __restrict__ W2, const float* __restrict__ W3,
    const float* __restrict__ b0, const float* __restrict__ b1,
    const float* __restrict__ b2, const float* __restrict__ b3)
{
    __shared__ float As[64][72];
    __shared__ float Ws[64][72];

    const int t     = blockIdx.y;
    const int ntile = blockIdx.x;
    const int gate  = ntile >> 3;
    const int u0    = (ntile & 7) << 6;
    const float* W    = (gate == 0) ? W0 : (gate == 1) ? W1 : (gate == 2) ? W2 : W3;
    const float* bias = (gate == 0) ? b0 : (gate == 1) ? b1 : (gate == 2) ? b2 : b3;

    const int tid = threadIdx.x;
    const int nq  = tid & 15;
    const int bq  = tid >> 4;

    unsigned long long acc[4][2];
    #pragma unroll
    for (int i = 0; i < 4; i++) { acc[i][0] = 0ull; acc[i][1] = 0ull; }

    for (int ec = 0; ec < Ee; ec += 64) {
        {
            int b = tid >> 2, q = tid & 3;
            const float4* src = (const float4*)(inp + ((size_t)b * Tt + t) * Ee + ec);
            float4* dst = (float4*)&As[b][0];
            #pragma unroll
            for (int i = 0; i < 4; i++) dst[q + i * 4] = src[q + i * 4];
        }
        {
            int er = tid >> 4, n4 = (tid & 15) << 2;
            #pragma unroll
            for (int p = 0; p < 4; p++) {
                int e = er + p * 16;
                *(float4*)&Ws[e][n4] = *(const float4*)&W[(size_t)(ec + e) * Uu + u0 + n4];
            }
        }
        __syncthreads();
        #pragma unroll 4
        for (int e = 0; e < 64; e++) {
            ulonglong2 w = *(const ulonglong2*)&Ws[e][nq << 2];
            #pragma unroll
            for (int bi = 0; bi < 4; bi++) {
                float a = As[(bq << 2) + bi][e];
                unsigned long long aa = pack2(a, a);
                acc[bi][0] = ffma2(aa, w.x, acc[bi][0]);
                acc[bi][1] = ffma2(aa, w.y, acc[bi][1]);
            }
        }
        __syncthreads();
    }

    float r[4][4];
    #pragma unroll
    for (int bi = 0; bi < 4; bi++) {
        unpack2(acc[bi][0], r[bi][0], r[bi][1]);
        unpack2(acc[bi][1], r[bi][2], r[bi][3]);
    }
    size_t base = (size_t)t * NG * Bb
                + (size_t)(gate * Uu + u0 + (nq << 2)) * Bb + (bq << 2);
    #pragma unroll
    for (int nj = 0; nj < 4; nj++) {
        float bv = bias[u0 + (nq << 2) + nj];
        float4 v = make_float4(r[0][nj] + bv, r[1][nj] + bv, r[2][nj] + bv, r[3][nj] + bv);
        *(float4*)&g_xp[base + (size_t)nj * Bb] = v;
    }
}

// =====================================================================================
// Kernel 2: pack recurrent weights (unchanged layout).
// g_wpack[blk*4096 + p*16 + ul*4 + g] = (W_g[2p][u], W_g[2p+1][u]), u = blk*4+ul.
// =====================================================================================
__global__ __launch_bounds__(256) void pack_kernel(
    const float* __restrict__ Wfh, const float* __restrict__ Wih,
    const float* __restrict__ Woh, const float* __restrict__ Wgh)
{
    const int blk = blockIdx.x;
    const int ubase = blk << 2;
    for (int i = threadIdx.x; i < 4096; i += 256) {
        int p = i >> 4, ul = (i >> 2) & 3, g = i & 3;
        int u = ubase + ul;
        const float* W = (g == 0) ? Wfh : (g == 1) ? Wih : (g == 2) ? Woh : Wgh;
        g_wpack[(size_t)blk * 4096 + i] =
            pack2(W[(size_t)(2 * p) * Uu + u], W[(size_t)(2 * p + 1) * Uu + u]);
    }
}

// =====================================================================================
// Kernel 3: ONE TIMESTEP, 128 CTAs x 512 threads.
// R8: register tiling. Thread = (ks 0..7, bg 0..15, ul 0..3): tile = 4 batches x 4
// gates, 32 k-pairs (k-range 64). Per k-pair: 2 LDG.128 h (4 b) + 2 LDG.128 w + 16
// ffma2 -> warp-LDG/SM drops 6144 -> 2048 (below the 4096-cyc fma floor); 16
// independent acc chains give the ILP that warp count used to provide.
// 8-way k-reduction: two-phase smem tree (32 KB). Graph edge = global sync.
// =====================================================================================
__global__ __launch_bounds__(512) void lstm_step_kernel(float* __restrict__ out, int t)
{
    __shared__ ulonglong2 red[4 * 64 * 8];            // 32 KB: [slot][r][8]
    const int tid = threadIdx.x;
    const int blk = blockIdx.x;

    const int ks = tid >> 6;             // 0..7 (warp-uniform: 2 warps per ks)
    const int r  = tid & 63;
    const int bg = r >> 2;
    const int ul = r & 3;
    const int b  = bg << 2;              // 4 batches per thread
    const int u  = (blk << 2) + ul;

    // ks==0 threads own the pointwise tail: issue xp/c loads early (float4, b-contig)
    float zf[4], zi[4], zo[4], zg[4], cv[4];
    if (ks == 0) {
        const float* xpt = g_xp + (size_t)t * NG * Bb + (size_t)u * Bb + b;
        float4 v;
        v = __ldg((const float4*)(xpt));                          zf[0]=v.x; zf[1]=v.y; zf[2]=v.z; zf[3]=v.w;
        v = __ldg((const float4*)(xpt + (size_t)(1*Uu)*Bb));      zi[0]=v.x; zi[1]=v.y; zi[2]=v.z; zi[3]=v.w;
        v = __ldg((const float4*)(xpt + (size_t)(2*Uu)*Bb));      zo[0]=v.x; zo[1]=v.y; zo[2]=v.z; zo[3]=v.w;
        v = __ldg((const float4*)(xpt + (size_t)(3*Uu)*Bb));      zg[0]=v.x; zg[1]=v.y; zg[2]=v.z; zg[3]=v.w;
        if (t > 0) {
            v = __ldg((const float4*)(g_cX + (size_t)u * Bb + b));
            cv[0]=v.x; cv[1]=v.y; cv[2]=v.z; cv[3]=v.w;
        } else { cv[0]=cv[1]=cv[2]=cv[3]=0.f; }
    }

    unsigned long long a[4][4];                       // [bi][gate] f32x2 k-pair partials
    #pragma unroll
    for (int bi = 0; bi < 4; bi++)
        #pragma unroll
        for (int g = 0; g < 4; g++) a[bi][g] = 0ull;

    if (t > 0) {
        // h pairs: g_hX[t&1][p][b], p = ks*32 + j ; this thread covers b..b+3
        const unsigned long long* hbase = g_hX[t & 1] + (size_t)(ks * 32) * Bb + b;
        const unsigned long long* wq = g_wpack + (size_t)blk * 4096 + (size_t)(ks * 32) * 16 + ul * 4;

        #pragma unroll 4
        for (int j = 0; j < 32; j++) {                // one k-pair per iter
            ulonglong2 h01 = __ldg((const ulonglong2*)(hbase + (size_t)j * Bb));      // b, b+1
            ulonglong2 h23 = __ldg((const ulonglong2*)(hbase + (size_t)j * Bb + 2));  // b+2, b+3
            ulonglong2 wA  = __ldg((const ulonglong2*)(wq + (size_t)j * 16));         // f, i
            ulonglong2 wB  = __ldg((const ulonglong2*)(wq + (size_t)j * 16 + 2));     // o, g
            a[0][0]=ffma2(h01.x,wA.x,a[0][0]); a[0][1]=ffma2(h01.x,wA.y,a[0][1]);
            a[0][2]=ffma2(h01.x,wB.x,a[0][2]); a[0][3]=ffma2(h01.x,wB.y,a[0][3]);
            a[1][0]=ffma2(h01.y,wA.x,a[1][0]); a[1][1]=ffma2(h01.y,wA.y,a[1][1]);
            a[1][2]=ffma2(h01.y,wB.x,a[1][2]); a[1][3]=ffma2(h01.y,wB.y,a[1][3]);
            a[2][0]=ffma2(h23.x,wA.x,a[2][0]); a[2][1]=ffma2(h23.x,wA.y,a[2][1]);
            a[2][2]=ffma2(h23.x,wB.x,a[2][2]); a[2][3]=ffma2(h23.x,wB.y,a[2][3]);
            a[3][0]=ffma2(h23.y,wA.x,a[3][0]); a[3][1]=ffma2(h23.y,wA.y,a[3][1]);
            a[3][2]=ffma2(h23.y,wB.x,a[3][2]); a[3][3]=ffma2(h23.y,wB.y,a[3][3]);
        }
    }

    // ---- two-phase 8->1 k-reduction through 32 KB smem ----
    // Phase 1: ks 4..7 -> slots 0..3; ks 0..3 absorb.
    if (ks >= 4) {
        ulonglong2* dst = &red[((ks - 4) * 64 + r) * 8];
        #pragma unroll
        for (int bi = 0; bi < 4; bi++) {
            dst[bi * 2 + 0] = make_ulonglong2(a[bi][0], a[bi][1]);
            dst[bi * 2 + 1] = make_ulonglong2(a[bi][2], a[bi][3]);
        }
    }
    __syncthreads();
    if (ks < 4) {
        const ulonglong2* src = &red[(ks * 64 + r) * 8];
        #pragma unroll
        for (int bi = 0; bi < 4; bi++) {
            ulonglong2 p0 = src[bi * 2 + 0], p1 = src[bi * 2 + 1];
            a[bi][0] = add2(a[bi][0], p0.x);  a[bi][1] = add2(a[bi][1], p0.y);
            a[bi][2] = add2(a[bi][2], p1.x);  a[bi][3] = add2(a[bi][3], p1.y);
        }
    }
    __syncthreads();
    // Phase 2: ks 1..3 -> slots 0..2; ks 0 absorbs.
    if (ks >= 1 && ks < 4) {
        ulonglong2* dst = &red[((ks - 1) * 64 + r) * 8];
        #pragma unroll
        for (int bi = 0; bi < 4; bi++) {
            dst[bi * 2 + 0] = make_ulonglong2(a[bi][0], a[bi][1]);
            dst[bi * 2 + 1] = make_ulonglong2(a[bi][2], a[bi][3]);
        }
    }
    __syncthreads();

    if (ks == 0) {
        #pragma unroll
        for (int s = 0; s < 3; s++) {
            const ulonglong2* src = &red[(s * 64 + r) * 8];
            #pragma unroll
            for (int bi = 0; bi < 4; bi++) {
                ulonglong2 p0 = src[bi * 2 + 0], p1 = src[bi * 2 + 1];
                a[bi][0] = add2(a[bi][0], p0.x);  a[bi][1] = add2(a[bi][1], p0.y);
                a[bi][2] = add2(a[bi][2], p1.x);  a[bi][3] = add2(a[bi][3], p1.y);
            }
        }
        float* hXf = (float*)g_hX[(t + 1) & 1];
        float4 cnew;
        float* cn = (float*)&cnew;
        #pragma unroll
        for (int bi = 0; bi < 4; bi++) {
            float f  = hadd2(a[bi][0]) + zf[bi];
            float i_ = hadd2(a[bi][1]) + zi[bi];
            float o  = hadd2(a[bi][2]) + zo[bi];
            float g  = hadd2(a[bi][3]) + zg[bi];
            f  = 1.f / (1.f + expf(-f));
            i_ = 1.f / (1.f + expf(-i_));
            o  = 1.f / (1.f + expf(-o));
            g  = 1.f / (1.f + expf(-g));
            float c = f * cv[bi] + i_ * g;
            float h = tanhf(c) * o;
            cn[bi] = c;
            // transposed h store for step t+1: element (p=u>>1, b+bi, half=u&1)
            hXf[(size_t)((u >> 1) * Bb + b + bi) * 2 + (u & 1)] = h;
            out[((size_t)(b + bi) * Tt + t) * Uu + u] = h;
        }
        *(float4*)(g_cX + (size_t)u * Bb + b) = cnew;
    }
}

// =====================================================================================
extern "C" void kernel_launch(void* const* d_in, const int* in_sizes, int n_in,
                              void* d_out, int out_size)
{
    const float* inp  = (const float*)d_in[0];
    const float* Wf_x = (const float*)d_in[1];
    const float* Wf_h = (const float*)d_in[2];
    const float* bf   = (const float*)d_in[3];
    const float* Wi_x = (const float*)d_in[4];
    const float* Wi_h = (const float*)d_in[5];
    const float* bi   = (const float*)d_in[6];
    const float* Wo_x = (const float*)d_in[7];
    const float* Wo_h = (const float*)d_in[8];
    const float* bo   = (const float*)d_in[9];
    const float* Wg_x = (const float*)d_in[10];
    const float* Wg_h = (const float*)d_in[11];
    const float* bg   = (const float*)d_in[12];
    float* out = (float*)d_out;

    dim3 g1(32, Tt);
    xproj_kernel<<<g1, 256>>>(inp, Wf_x, Wi_x, Wo_x, Wg_x, bf, bi, bo, bg);
    pack_kernel<<<NBLK, 256>>>(Wf_h, Wi_h, Wo_h, Wg_h);
    for (int t = 0; t < Tt; t++)
        lstm_step_kernel<<<NBLK, 512>>>(out, t);
}

// round 9
// speedup vs baseline: 1.0080x; 1.0080x over previous
#include <cuda_runtime.h>

#define Bb 64
#define Tt 512
#define Ee 256
#define Uu 512
#define NG 2048   // 4*U
#define NBLK 128  // persistent grid: 128 CTAs <= 148 SMs, 1 CTA/SM => co-resident wave

// Scratch (device globals: allocation-free per harness rules)
__device__ float g_xp[(size_t)Tt * NG * Bb];          // [t][n][b], n = gate*U + u (256 MB)
__device__ __align__(16) unsigned long long g_hX[2][256 * Bb];  // h, k-pair transposed:
                                                      // [p][b] = (h[b][2p], h[b][2p+1])
__device__ __align__(16) unsigned long long g_wpack[NBLK * 4096]; // packed Wh (4 MB)
__device__ unsigned g_bar;                            // monotone grid-barrier counter

// ---------- packed f32x2 helpers (Blackwell FFMA2/FADD2) ----------
static __device__ __forceinline__ unsigned long long pack2(float a, float b) {
    unsigned long long r;
    unsigned ai = __float_as_uint(a), bi = __float_as_uint(b);
    asm("mov.b64 %0, {%1, %2};" : "=l"(r) : "r"(ai), "r"(bi));
    return r;
}
static __device__ __forceinline__ void unpack2(unsigned long long v, float& a, float& b) {
    unsigned ai, bi;
    asm("mov.b64 {%0, %1}, %2;" : "=r"(ai), "=r"(bi) : "l"(v));
    a = __uint_as_float(ai); b = __uint_as_float(bi);
}
static __device__ __forceinline__ unsigned long long ffma2(
    unsigned long long a, unsigned long long b, unsigned long long c) {
    unsigned long long d;
    asm("fma.rn.f32x2 %0, %1, %2, %3;" : "=l"(d) : "l"(a), "l"(b), "l"(c));
    return d;
}
static __device__ __forceinline__ unsigned long long add2(
    unsigned long long a, unsigned long long b) {
    unsigned long long d;
    asm("add.rn.f32x2 %0, %1, %2;" : "=l"(d) : "l"(a), "l"(b));
    return d;
}
static __device__ __forceinline__ float hadd2(unsigned long long v) {
    float a, b; unpack2(v, a, b); return a + b;
}
static __device__ __forceinline__ unsigned long long ldcg_u64(const unsigned long long* p) {
    unsigned long long v;
    asm volatile("ld.global.cg.b64 %0, [%1];" : "=l"(v) : "l"(p));
    return v;
}
static __device__ __forceinline__ ulonglong2 ldcg_u128(const ulonglong2* p) {
    ulonglong2 v;
    asm volatile("ld.global.cg.v2.b64 {%0, %1}, [%2];" : "=l"(v.x), "=l"(v.y) : "l"(p));
    return v;
}

// =====================================================================================
// Kernel 1: x_proj (unchanged; proven). Output xp[t][n][b] (+bias), b contiguous.
// =====================================================================================
__global__ __launch_bounds__(256) void xproj_kernel(
    const float* __restrict__ inp,
    const float* __restrict__ W0, const float* __restrict__ W1,
    const float* __restrict__ W2, const float* __restrict__ W3,
    const float* __restrict__ b0, const float* __restrict__ b1,
    const float* __restrict__ b2, const float* __restrict__ b3)
{
    __shared__ float As[64][72];
    __shared__ float Ws[64][72];

    const int t     = blockIdx.y;
    const int ntile = blockIdx.x;
    const int gate  = ntile >> 3;
    const int u0    = (ntile & 7) << 6;
    const float* W    = (gate == 0) ? W0 : (gate == 1) ? W1 : (gate == 2) ? W2 : W3;
    const float* bias = (gate == 0) ? b0 : (gate == 1) ? b1 : (gate == 2) ? b2 : b3;

    const int tid = threadIdx.x;
    const int nq  = tid & 15;
    const int bq  = tid >> 4;

    unsigned long long acc[4][2];
    #pragma unroll
    for (int i = 0; i < 4; i++) { acc[i][0] = 0ull; acc[i][1] = 0ull; }

    for (int ec = 0; ec < Ee; ec += 64) {
        {
            int b = tid >> 2, q = tid & 3;
            const float4* src = (const float4*)(inp + ((size_t)b * Tt + t) * Ee + ec);
            float4* dst = (float4*)&As[b][0];
            #pragma unroll
            for (int i = 0; i < 4; i++) dst[q + i * 4] = src[q + i * 4];
        }
        {
            int er = tid >> 4, n4 = (tid & 15) << 2;
            #pragma unroll
            for (int p = 0; p < 4; p++) {
                int e = er + p * 16;
                *(float4*)&Ws[e][n4] = *(const float4*)&W[(size_t)(ec + e) * Uu + u0 + n4];
            }
        }
        __syncthreads();
        #pragma unroll 4
        for (int e = 0; e < 64; e++) {
            ulonglong2 w = *(const ulonglong2*)&Ws[e][nq << 2];
            #pragma unroll
            for (int bi = 0; bi < 4; bi++) {
                float a = As[(bq << 2) + bi][e];
                unsigned long long aa = pack2(a, a);
                acc[bi][0] = ffma2(aa, w.x, acc[bi][0]);
                acc[bi][1] = ffma2(aa, w.y, acc[bi][1]);
            }
        }
        __syncthreads();
    }

    float r[4][4];
    #pragma unroll
    for (int bi = 0; bi < 4; bi++) {
        unpack2(acc[bi][0], r[bi][0], r[bi][1]);
        unpack2(acc[bi][1], r[bi][2], r[bi][3]);
    }
    size_t base = (size_t)t * NG * Bb
                + (size_t)(gate * Uu + u0 + (nq << 2)) * Bb + (bq << 2);
    #pragma unroll
    for (int nj = 0; nj < 4; nj++) {
        float bv = bias[u0 + (nq << 2) + nj];
        float4 v = make_float4(r[0][nj] + bv, r[1][nj] + bv, r[2][nj] + bv, r[3][nj] + bv);
        *(float4*)&g_xp[base + (size_t)nj * Bb] = v;
    }
}

// =====================================================================================
// Kernel 2: pack recurrent weights (unchanged layout).
// g_wpack[blk*4096 + p*16 + ul*4 + g] = (W_g[2p][u], W_g[2p+1][u]), u = blk*4+ul.
// =====================================================================================
__global__ __launch_bounds__(256) void pack_kernel(
    const float* __restrict__ Wfh, const float* __restrict__ Wih,
    const float* __restrict__ Woh, const float* __restrict__ Wgh)
{
    const int blk = blockIdx.x;
    const int ubase = blk << 2;
    for (int i = threadIdx.x; i < 4096; i += 256) {
        int p = i >> 4, ul = (i >> 2) & 3, g = i & 3;
        int u = ubase + ul;
        const float* W = (g == 0) ? Wfh : (g == 1) ? Wih : (g == 2) ? Woh : Wgh;
        g_wpack[(size_t)blk * 4096 + i] =
            pack2(W[(size_t)(2 * p) * Uu + u], W[(size_t)(2 * p + 1) * Uu + u]);
    }
}

// =====================================================================================
// Grid barrier: monotone counter; release fence + lane-0 acquire spin. Wrap-safe.
// Correct for any launch count / graph replays (target derived from fetched value).
// =====================================================================================
static __device__ __forceinline__ void grid_barrier()
{
    __syncthreads();
    if (threadIdx.x == 0) {
        __threadfence();                               // publish h stores to gpu scope
        unsigned old = atomicAdd(&g_bar, 1u);
        unsigned target = old - (old & (NBLK - 1)) + NBLK;
        unsigned v;
        do {
            asm volatile("ld.acquire.gpu.u32 %0, [%1];" : "=r"(v) : "l"(&g_bar) : "memory");
        } while ((int)(v - target) < 0);
    }
    __syncthreads();
}

// =====================================================================================
// Kernel 3: PERSISTENT recurrence. 128 CTAs x 512 threads, one wave (1 CTA/SM).
// Why persistent: R5-R8 showed launch-per-step pins the step at ~15us because L1D is
// flushed per launch (all weight loads re-fetch L2) + per-node overhead. Here the
// 32KB/SM weight slice L1-caches ONCE (step 1) and stays hot for all 512 steps.
// Thread = (ks 0..7, bg 0..15, ul 0..3): tile 4 b x 4 gates, 32 k-pairs. Per k-pair:
// 2 LDG.128 h (__ldcg: L1 incoherent across barrier) + 2 LDG.128 w (__ldg: L1-hot)
// + 16 ffma2. c LIVES IN REGISTERS for the whole kernel. 8->1 k-reduce via smem.
// =====================================================================================
__global__ __launch_bounds__(512) void lstm_persist_kernel(float* __restrict__ out)
{
    __shared__ ulonglong2 red[4 * 64 * 8];            // 32 KB: [slot][r][8]
    const int tid = threadIdx.x;
    const int blk = blockIdx.x;

    const int ks = tid >> 6;             // 0..7 (warp-uniform: 2 warps per ks)
    const int r  = tid & 63;
    const int bg = r >> 2;
    const int ul = r & 3;
    const int b  = bg << 2;              // 4 batches per thread
    const int u  = (blk << 2) + ul;

    const unsigned long long* wq =
        g_wpack + (size_t)blk * 4096 + (size_t)(ks * 32) * 16 + ul * 4;

    float cv0 = 0.f, cv1 = 0.f, cv2 = 0.f, cv3 = 0.f;     // cell state: registers only

    for (int t = 0; t < Tt; t++) {
        // ks==0 threads own the pointwise tail: issue xp loads early
        float zf[4], zi[4], zo[4], zg[4];
        if (ks == 0) {
            const float* xpt = g_xp + (size_t)t * NG * Bb + (size_t)u * Bb + b;
            float4 v;
            v = __ldg((const float4*)(xpt));                     zf[0]=v.x; zf[1]=v.y; zf[2]=v.z; zf[3]=v.w;
            v = __ldg((const float4*)(xpt + (size_t)(1*Uu)*Bb)); zi[0]=v.x; zi[1]=v.y; zi[2]=v.z; zi[3]=v.w;
            v = __ldg((const float4*)(xpt + (size_t)(2*Uu)*Bb)); zo[0]=v.x; zo[1]=v.y; zo[2]=v.z; zo[3]=v.w;
            v = __ldg((const float4*)(xpt + (size_t)(3*Uu)*Bb)); zg[0]=v.x; zg[1]=v.y; zg[2]=v.z; zg[3]=v.w;
        }

        unsigned long long a[4][4];
        #pragma unroll
        for (int bi = 0; bi < 4; bi++)
            #pragma unroll
            for (int g = 0; g < 4; g++) a[bi][g] = 0ull;

        if (t > 0) {
            const unsigned long long* hbase = g_hX[t & 1] + (size_t)(ks * 32) * Bb + b;
            #pragma unroll 4
            for (int j = 0; j < 32; j++) {            // one k-pair per iter
                ulonglong2 h01 = ldcg_u128((const ulonglong2*)(hbase + (size_t)j * Bb));
                ulonglong2 h23 = ldcg_u128((const ulonglong2*)(hbase + (size_t)j * Bb + 2));
                ulonglong2 wA  = __ldg((const ulonglong2*)(wq + (size_t)j * 16));       // f,i
                ulonglong2 wB  = __ldg((const ulonglong2*)(wq + (size_t)j * 16 + 2));   // o,g
                a[0][0]=ffma2(h01.x,wA.x,a[0][0]); a[0][1]=ffma2(h01.x,wA.y,a[0][1]);
                a[0][2]=ffma2(h01.x,wB.x,a[0][2]); a[0][3]=ffma2(h01.x,wB.y,a[0][3]);
                a[1][0]=ffma2(h01.y,wA.x,a[1][0]); a[1][1]=ffma2(h01.y,wA.y,a[1][1]);
                a[1][2]=ffma2(h01.y,wB.x,a[1][2]); a[1][3]=ffma2(h01.y,wB.y,a[1][3]);
                a[2][0]=ffma2(h23.x,wA.x,a[2][0]); a[2][1]=ffma2(h23.x,wA.y,a[2][1]);
                a[2][2]=ffma2(h23.x,wB.x,a[2][2]); a[2][3]=ffma2(h23.x,wB.y,a[2][3]);
                a[3][0]=ffma2(h23.y,wA.x,a[3][0]); a[3][1]=ffma2(h23.y,wA.y,a[3][1]);
                a[3][2]=ffma2(h23.y,wB.x,a[3][2]); a[3][3]=ffma2(h23.y,wB.y,a[3][3]);
            }
        }

        // ---- two-phase 8->1 k-reduction through 32 KB smem ----
        if (ks >= 4) {
            ulonglong2* dst = &red[((ks - 4) * 64 + r) * 8];
            #pragma unroll
            for (int bi = 0; bi < 4; bi++) {
                dst[bi * 2 + 0] = make_ulonglong2(a[bi][0], a[bi][1]);
                dst[bi * 2 + 1] = make_ulonglong2(a[bi][2], a[bi][3]);
            }
        }
        __syncthreads();
        if (ks < 4) {
            const ulonglong2* src = &red[(ks * 64 + r) * 8];
            #pragma unroll
            for (int bi = 0; bi < 4; bi++) {
                ulonglong2 p0 = src[bi * 2 + 0], p1 = src[bi * 2 + 1];
                a[bi][0] = add2(a[bi][0], p0.x);  a[bi][1] = add2(a[bi][1], p0.y);
                a[bi][2] = add2(a[bi][2], p1.x);  a[bi][3] = add2(a[bi][3], p1.y);
            }
        }
        __syncthreads();
        if (ks >= 1 && ks < 4) {
            ulonglong2* dst = &red[((ks - 1) * 64 + r) * 8];
            #pragma unroll
            for (int bi = 0; bi < 4; bi++) {
                dst[bi * 2 + 0] = make_ulonglong2(a[bi][0], a[bi][1]);
                dst[bi * 2 + 1] = make_ulonglong2(a[bi][2], a[bi][3]);
            }
        }
        __syncthreads();

        if (ks == 0) {
            #pragma unroll
            for (int s = 0; s < 3; s++) {
                const ulonglong2* src = &red[(s * 64 + r) * 8];
                #pragma unroll
                for (int bi = 0; bi < 4; bi++) {
                    ulonglong2 p0 = src[bi * 2 + 0], p1 = src[bi * 2 + 1];
                    a[bi][0] = add2(a[bi][0], p0.x);  a[bi][1] = add2(a[bi][1], p0.y);
                    a[bi][2] = add2(a[bi][2], p1.x);  a[bi][3] = add2(a[bi][3], p1.y);
                }
            }
            float* hXf = (float*)g_hX[(t + 1) & 1];
            #pragma unroll
            for (int bi = 0; bi < 4; bi++) {
                float f  = hadd2(a[bi][0]) + zf[bi];
                float i_ = hadd2(a[bi][1]) + zi[bi];
                float o  = hadd2(a[bi][2]) + zo[bi];
                float g  = hadd2(a[bi][3]) + zg[bi];
                f  = 1.f / (1.f + expf(-f));
                i_ = 1.f / (1.f + expf(-i_));
                o  = 1.f / (1.f + expf(-o));
                g  = 1.f / (1.f + expf(-g));
                float cprev = (bi == 0) ? cv0 : (bi == 1) ? cv1 : (bi == 2) ? cv2 : cv3;
                float c = f * cprev + i_ * g;
                if (bi == 0) cv0 = c; else if (bi == 1) cv1 = c;
                else if (bi == 2) cv2 = c; else cv3 = c;
                float h = tanhf(c) * o;
                // transposed h store for step t+1: element (p=u>>1, b+bi, half=u&1)
                hXf[(size_t)((u >> 1) * Bb + b + bi) * 2 + (u & 1)] = h;
                out[((size_t)(b + bi) * Tt + t) * Uu + u] = h;
            }
        }

        if (t != Tt - 1) grid_barrier();
    }
}

// =====================================================================================
extern "C" void kernel_launch(void* const* d_in, const int* in_sizes, int n_in,
                              void* d_out, int out_size)
{
    const float* inp  = (const float*)d_in[0];
    const float* Wf_x = (const float*)d_in[1];
    const float* Wf_h = (const float*)d_in[2];
    const float* bf   = (const float*)d_in[3];
    const float* Wi_x = (const float*)d_in[4];
    const float* Wi_h = (const float*)d_in[5];
    const float* bi   = (const float*)d_in[6];
    const float* Wo_x = (const float*)d_in[7];
    const float* Wo_h = (const float*)d_in[8];
    const float* bo   = (const float*)d_in[9];
    const float* Wg_x = (const float*)d_in[10];
    const float* Wg_h = (const float*)d_in[11];
    const float* bg   = (const float*)d_in[12];
    float* out = (float*)d_out;

    dim3 g1(32, Tt);
    xproj_kernel<<<g1, 256>>>(inp, Wf_x, Wi_x, Wo_x, Wg_x, bf, bi, bo, bg);
    pack_kernel<<<NBLK, 256>>>(Wf_h, Wi_h, Wo_h, Wg_h);
    lstm_persist_kernel<<<NBLK, 512>>>(out);
}